// round 10
// baseline (speedup 1.0000x reference)
#include <cuda_runtime.h>
#include <cstdint>
#include <math.h>

#define NN 8192
#define EPSF 1e-20f
#define NITER 32
#define NCTA 148
#define NTHR 512
#define ROWB 32768               // bytes per H row
#define RDEPTH 4                 // TMA ring slots (power of 2)

// dynamic smem layout
#define SM_MBAR 0                // 4 mbarriers, 16B stride
#define SM_WRED 128              // 2 x 16 warp partials (double-buffered)
#define SM_GPART 1024            // 512 floats (phase-B group partials)
#define SM_SRED 3072             // 64 floats (phase-B rs partials)
#define SM_T    3328             // 56 floats: this CTA's t_r = (Hp)_row
#define SM_QH   3584             // 56 floats: incremental q_hat for own rows
#define SM_RING 4096             // RDEPTH x 32768 row buffers
#define SMEM_TOTAL (SM_RING + RDEPTH * ROWB)

// ---- device scratch (no allocations allowed) ----
__device__ float g_slab[NCTA * NN];     // 4.85 MB per-CTA Ap partial slabs
__device__ float g_ttpart[NCTA];
__device__ float g_rspart[NCTA];
__device__ float g_r[NN], g_p[NN], g_v[NN], g_qh[NN];
__device__ float g_msum[8];             // time-domain metric sums
__device__ float g_fftsum[8];
__device__ unsigned g_flags[NCTA];      // grid-barrier flags (monotone across replays)

// ---------------- PTX helpers ----------------
__device__ __forceinline__ uint32_t sm_u32(const void* p) {
    uint32_t a;
    asm("{ .reg .u64 t; cvta.to.shared.u64 t, %1; cvt.u32.u64 %0, t; }" : "=r"(a) : "l"(p));
    return a;
}
#define MB_INIT(a, c) \
    asm volatile("mbarrier.init.shared.b64 [%0], %1;" :: "r"(a), "r"(c) : "memory")
#define MB_EXPECT(a, b) \
    asm volatile("mbarrier.arrive.expect_tx.shared.b64 _, [%0], %1;" :: "r"(a), "r"(b) : "memory")
#define BULK_LD(dst, src, sz, mb) \
    asm volatile("cp.async.bulk.shared::cta.global.mbarrier::complete_tx::bytes [%0], [%1], %2, [%3];" \
                 :: "r"(dst), "l"(src), "r"(sz), "r"(mb) : "memory")

__device__ __forceinline__ void mb_wait(uint32_t mbar, uint32_t parity) {
    uint32_t done;
    do {
        asm volatile("{ .reg .pred p; mbarrier.try_wait.parity.acquire.cta.shared::cta.b64 p, [%1], %2; "
                     "selp.b32 %0, 1, 0, p; }" : "=r"(done) : "r"(mbar), "r"(parity) : "memory");
    } while (!done);
}

__device__ __forceinline__ void grid_bar(int tid, int bid, unsigned gen) {
    __syncthreads();
    if (tid == 0)
        asm volatile("st.global.release.gpu.u32 [%0], %1;" :: "l"(&g_flags[bid]), "r"(gen) : "memory");
    if (tid < NCTA) {
        unsigned v;
        do {
            asm volatile("ld.global.acquire.gpu.u32 %0, [%1];" : "=r"(v) : "l"(&g_flags[tid]) : "memory");
        } while ((int)(v - gen) < 0);
    }
    __syncthreads();
}

// ---------------------------------------------------------------------------
// One streaming pass over this CTA's rows via the TMA ring.  (R7 version —
// do not modify: every restructuring of this loop has regressed.)
// MODE 0: tr = dot(row, preg) -> apa += tr*row, ta += tr*tr, smem t[r] = tr
// MODE 1: tr = xvec[row]      -> apa += tr*row                (setup b = H^T x)
// ---------------------------------------------------------------------------
template<int MODE>
__device__ __forceinline__ float run_pass(const float* __restrict__ H, char* smem,
                                          uint32_t smb, int tid, int row0, int nrows,
                                          unsigned& gq, const float4* preg, float4* apa,
                                          const float* __restrict__ xvec) {
    float* wred = (float*)(smem + SM_WRED);
    float* smt  = (float*)(smem + SM_T);
#pragma unroll
    for (int c = 0; c < 4; c++) apa[c] = make_float4(0.f, 0.f, 0.f, 0.f);
    float ta = 0.f;
    if (tid == 0) {
        int npro = nrows < RDEPTH ? nrows : RDEPTH;
        for (int k = 0; k < npro; k++) {
            unsigned u = gq + k;
            uint32_t slot = u & (RDEPTH - 1);
            uint32_t mb = smb + SM_MBAR + slot * 16;
            MB_EXPECT(mb, ROWB);
            BULK_LD(smb + SM_RING + slot * ROWB,
                    (const void*)(H + (size_t)(row0 + k) * NN), (uint32_t)ROWB, mb);
        }
    }
    for (int r = 0; r < nrows; r++) {
        unsigned u = gq + r;
        uint32_t slot = u & (RDEPTH - 1);
        mb_wait(smb + SM_MBAR + slot * 16, (u >> 2) & 1);
        const float4* row4 = (const float4*)(smem + SM_RING + slot * ROWB);
        float4 st[4];
        float d = 0.f;
#pragma unroll
        for (int c = 0; c < 4; c++) {
            st[c] = row4[tid + NTHR * c];
            if (MODE == 0)
                d += st[c].x * preg[c].x + st[c].y * preg[c].y
                   + st[c].z * preg[c].z + st[c].w * preg[c].w;
        }
        float tr;
        if (MODE == 1) {
            tr = xvec[row0 + r];
            __syncthreads();            // all LDS of this slot done before reissue
        } else {
            for (int o = 16; o; o >>= 1) d += __shfl_xor_sync(0xffffffffu, d, o);
            if ((tid & 31) == 0) wred[(r & 1) * 16 + (tid >> 5)] = d;
            __syncthreads();
        }
        if (tid == 0 && r + RDEPTH < nrows) {
            uint32_t mb = smb + SM_MBAR + slot * 16;   // slot(u+RDEPTH) == slot(u)
            MB_EXPECT(mb, ROWB);
            BULK_LD(smb + SM_RING + slot * ROWB,
                    (const void*)(H + (size_t)(row0 + r + RDEPTH) * NN), (uint32_t)ROWB, mb);
        }
        if (MODE == 0) {
            tr = 0.f;
#pragma unroll
            for (int w = 0; w < 16; w++) tr += wred[(r & 1) * 16 + w];
            if (tid == 0) smt[r] = tr;
        }
#pragma unroll
        for (int c = 0; c < 4; c++) {
            apa[c].x += tr * st[c].x; apa[c].y += tr * st[c].y;
            apa[c].z += tr * st[c].z; apa[c].w += tr * st[c].w;
        }
        ta += tr * tr;
    }
    gq += (unsigned)nrows;
    return ta;
}

// phase B: slab reduce over own columns + vector update (or setup init)
__device__ __forceinline__ void phaseB(char* smem, int tid, int bid, int c0, int nc,
                                       float alpha, bool setup) {
    float* sgp = (float*)(smem + SM_GPART);
    float* sred = (float*)(smem + SM_SRED);
    int g = tid >> 6, tc = tid & 63;
    float part = 0.f;
    if (tc < nc) {
        for (int cs = g; cs < NCTA; cs += 8) part += g_slab[(size_t)cs * NN + c0 + tc];
    }
    sgp[g * 64 + tc] = part;
    __syncthreads();
    if (tid < nc) {
        float ap = 0.f;
#pragma unroll
        for (int gg = 0; gg < 8; gg++) ap += sgp[gg * 64 + tid];
        int j = c0 + tid;
        float rn;
        if (setup) {
            g_v[j] = 0.f;
            g_r[j] = ap;      // r = b
            rn = ap;
        } else {
            g_v[j] += alpha * g_p[j];
            rn = g_r[j] - alpha * ap;
            g_r[j] = rn;
        }
        sred[tid] = rn * rn;
    }
    __syncthreads();
    if (tid == 0) {
        float s = 0.f;
        for (int i = 0; i < nc; i++) s += sred[i];
        g_rspart[bid] = s;
    }
}

// ---------------------------------------------------------------------------
// The persistent CG kernel: setup + 32 iterations; q_hat accumulated in smem.
// ---------------------------------------------------------------------------
__global__ void __launch_bounds__(NTHR, 1) cgm_persistent(const float* __restrict__ H,
                                                          const float* __restrict__ x) {
    extern __shared__ char smem[];
    int tid = threadIdx.x, bid = blockIdx.x;
    uint32_t smb = sm_u32(smem);
    float* smt = (float*)(smem + SM_T);
    float* smqh = (float*)(smem + SM_QH);
    if (tid == 0) {
        for (int s = 0; s < RDEPTH; s++) MB_INIT(smb + SM_MBAR + s * 16, 1);
    }
    if (tid < 64) smqh[tid] = 0.f;
    __syncthreads();
    unsigned base_gen = g_flags[bid];    // all flags equal at launch (monotone)
    unsigned barn = 0;
    unsigned gq = 0;

    int row0, nrows;
    if (bid < 52) { row0 = bid * 56; nrows = 56; }
    else          { row0 = 2912 + (bid - 52) * 55; nrows = 55; }
    int c0 = row0, nc = nrows;           // same partition for columns

    float4 apa[4], preg[4];
    float rs = 0.f;

    // ---- setup: b = H^T x (rank-1 streaming), then r=b, v=0, rs0 partials ----
    run_pass<1>(H, smem, smb, tid, row0, nrows, gq, preg, apa, x);
    {
        float4* slab4 = (float4*)(g_slab + (size_t)bid * NN);
#pragma unroll
        for (int c = 0; c < 4; c++) slab4[tid + NTHR * c] = apa[c];
    }
    grid_bar(tid, bid, base_gen + (++barn));
    phaseB(smem, tid, bid, c0, nc, 0.f, true);
    grid_bar(tid, bid, base_gen + (++barn));

    for (int it = 0; it < NITER; it++) {
        // ---- A: beta (redundant, fixed order), p update (registers + gmem) ----
        float rs_new = 0.f;
        for (int c = 0; c < NCTA; c++) rs_new += g_rspart[c];
        float beta = (it == 0) ? 0.f : rs_new / (rs + EPSF);
        rs = rs_new;
#pragma unroll
        for (int c = 0; c < 4; c++) {
            float4 rr = ((const float4*)g_r)[tid + NTHR * c];
            if (it == 0) preg[c] = rr;
            else preg[c] = make_float4(rr.x + beta * preg[c].x, rr.y + beta * preg[c].y,
                                       rr.z + beta * preg[c].z, rr.w + beta * preg[c].w);
            ((float4*)g_p)[tid + NTHR * c] = preg[c];
        }
        // ---- matvec: slab partials of H^T(Hp), tt partials, smem t ----
        float ta = run_pass<0>(H, smem, smb, tid, row0, nrows, gq, preg, apa, nullptr);
        {
            float4* slab4 = (float4*)(g_slab + (size_t)bid * NN);
#pragma unroll
            for (int c = 0; c < 4; c++) slab4[tid + NTHR * c] = apa[c];
        }
        if (tid == 0) g_ttpart[bid] = ta;
        grid_bar(tid, bid, base_gen + (++barn));

        // ---- B: alpha (redundant), qh += alpha*t, Ap reduce + v,r + rs ----
        float tt = 0.f;
        for (int c = 0; c < NCTA; c++) tt += g_ttpart[c];
        float alpha = rs / (tt + EPSF);
        if (tid < nrows) smqh[tid] += alpha * smt[tid];
        phaseB(smem, tid, bid, c0, nc, alpha, false);
        grid_bar(tid, bid, base_gen + (++barn));
    }

    // ---- final: write accumulated q_hat (== H v up to fp rounding) ----
    if (tid < nrows) g_qh[row0 + tid] = smqh[tid];
}

// ---------------------------------------------------------------------------
// Fused tail kernel 1: blocks 0-3 = FFT modes; block 4 = time-domain metrics.
// ---------------------------------------------------------------------------
__global__ void __launch_bounds__(1024) metrics_fft_kernel(const float* __restrict__ x,
                                                           const float* __restrict__ qt,
                                                           const float* __restrict__ vt) {
    int tid = threadIdx.x;
    if (blockIdx.x == 4) {
        // time-domain sums: s0=(qh-x)^2 s1=|qh-qt| s2=(qh-qt)^2 s3=qt^2
        //                   s4=|v-vt|  s5=(v-vt)^2 s6=vt^2
        float acc[7] = {0.f, 0.f, 0.f, 0.f, 0.f, 0.f, 0.f};
        for (int j = tid; j < NN; j += 1024) {
            float qh = g_qh[j], vv = g_v[j];
            float qtj = qt[j], vtj = vt[j];
            float d0 = qh - x[j];
            float d1 = qh - qtj;
            float d2 = vv - vtj;
            acc[0] += d0 * d0;
            acc[1] += fabsf(d1);
            acc[2] += d1 * d1;
            acc[3] += qtj * qtj;
            acc[4] += fabsf(d2);
            acc[5] += d2 * d2;
            acc[6] += vtj * vtj;
        }
        __shared__ float red[1024];
#pragma unroll
        for (int s = 0; s < 7; s++) {
            red[tid] = acc[s];
            __syncthreads();
            for (int o = 512; o > 0; o >>= 1) {
                if (tid < o) red[tid] += red[tid + o];
                __syncthreads();
            }
            if (tid == 0) g_msum[s] = red[0];
            __syncthreads();
        }
        return;
    }

    // FFT blocks: 8192-pt real FFT via 4096-pt complex FFT (pack even/odd)
    // mode 0: qh - qt ; 1: qt ; 2: v - vt ; 3: vt
    __shared__ float2 Z[4096];
    __shared__ float red[1024];
    int mode = blockIdx.x;

    for (int n = tid; n < 4096; n += 1024) {
        int i0 = 2 * n, i1 = 2 * n + 1;
        float a, b;
        if (mode == 0)      { a = g_qh[i0] - qt[i0]; b = g_qh[i1] - qt[i1]; }
        else if (mode == 1) { a = qt[i0];            b = qt[i1]; }
        else if (mode == 2) { a = g_v[i0] - vt[i0];  b = g_v[i1] - vt[i1]; }
        else                { a = vt[i0];            b = vt[i1]; }
        int r = (int)(__brev((unsigned)n) >> 20);
        Z[r] = make_float2(a, b);
    }
    __syncthreads();

    for (int half = 1; half < 4096; half <<= 1) {
        for (int i = tid; i < 2048; i += 1024) {
            int pos = i & (half - 1);
            int idx1 = ((i ^ pos) << 1) | pos;
            int idx2 = idx1 + half;
            float s, c;
            sincospif((float)pos / (float)half, &s, &c);
            float2 z2 = Z[idx2];
            float2 t = make_float2(c * z2.x + s * z2.y, c * z2.y - s * z2.x);
            float2 z1 = Z[idx1];
            Z[idx2] = make_float2(z1.x - t.x, z1.y - t.y);
            Z[idx1] = make_float2(z1.x + t.x, z1.y + t.y);
        }
        __syncthreads();
    }

    float sabs = 0.f, ssq = 0.f;
    for (int k = tid; k <= 4096; k += 1024) {
        float2 Zk = Z[k & 4095];
        float2 Zm = Z[(4096 - k) & 4095];
        float2 Zmc = make_float2(Zm.x, -Zm.y);
        float2 Fe = make_float2(0.5f * (Zk.x + Zmc.x), 0.5f * (Zk.y + Zmc.y));
        float2 Fd = make_float2(Zk.x - Zmc.x, Zk.y - Zmc.y);
        float2 Fo = make_float2(0.5f * Fd.y, -0.5f * Fd.x);
        float s, c;
        sincospif((float)k / 4096.0f, &s, &c);
        float Xr = Fe.x + (c * Fo.x + s * Fo.y);
        float Xi = Fe.y + (c * Fo.y - s * Fo.x);
        float m2 = Xr * Xr + Xi * Xi;
        sabs += sqrtf(m2);
        ssq += m2;
    }
    red[tid] = sabs;
    __syncthreads();
    for (int s = 512; s > 0; s >>= 1) {
        if (tid < s) red[tid] += red[tid + s];
        __syncthreads();
    }
    if (tid == 0) g_fftsum[2 * mode] = red[0];
    __syncthreads();
    red[tid] = ssq;
    __syncthreads();
    for (int s = 512; s > 0; s >>= 1) {
        if (tid < s) red[tid] += red[tid + s];
        __syncthreads();
    }
    if (tid == 0) g_fftsum[2 * mode + 1] = red[0];
}

// ---------------------------------------------------------------------------
// Fused tail kernel 2: copy v (all blocks) + scalars (block 0 / thread 0).
// ---------------------------------------------------------------------------
__global__ void finalize_out_kernel(float* __restrict__ out, int out_size) {
    int j = blockIdx.x * 128 + threadIdx.x;
    if (j < out_size) {
        if (j < NN) out[j] = g_v[j];
        else if (j >= NN + 11) out[j] = 0.f;
    }
    if (blockIdx.x == 0 && threadIdx.x == 0) {
        float res[11];
        res[0]  = sqrtf(g_msum[0]);
        res[1]  = g_msum[1] / (float)NN;
        res[2]  = g_msum[2] / (g_msum[3] + EPSF);
        res[3]  = g_msum[4] / (float)NN;
        res[4]  = g_msum[5] / (g_msum[6] + EPSF);
        res[5]  = g_msum[2] / (float)NN;
        res[6]  = g_msum[5] / (float)NN;
        res[7]  = g_fftsum[0] / 4097.0f;
        res[8]  = g_fftsum[1] / (g_fftsum[3] + EPSF);
        res[9]  = g_fftsum[4] / 4097.0f;
        res[10] = g_fftsum[5] / (g_fftsum[7] + EPSF);
        for (int k = 0; k < 11; k++)
            if (NN + k < out_size) out[NN + k] = res[k];
    }
}

extern "C" void kernel_launch(void* const* d_in, const int* in_sizes, int n_in,
                              void* d_out, int out_size) {
    const float* H = nullptr;
    const float* x = nullptr;
    const float* vt = nullptr;
    const float* qt = nullptr;
    int vecseen = 0;
    for (int i = 0; i < n_in; i++) {
        if (in_sizes[i] == NN * NN) {
            H = (const float*)d_in[i];
        } else if (in_sizes[i] == NN) {
            if (vecseen == 0)      x  = (const float*)d_in[i];
            else if (vecseen == 1) vt = (const float*)d_in[i];
            else if (vecseen == 2) qt = (const float*)d_in[i];
            vecseen++;
        }
    }
    float* out = (float*)d_out;

    cudaFuncSetAttribute(cgm_persistent, cudaFuncAttributeMaxDynamicSharedMemorySize,
                         SMEM_TOTAL);

    cgm_persistent<<<NCTA, NTHR, SMEM_TOTAL>>>(H, x);
    metrics_fft_kernel<<<5, 1024>>>(x, qt, vt);
    {
        int nblk = (out_size + 127) / 128;
        if (nblk < 1) nblk = 1;
        finalize_out_kernel<<<nblk, 128>>>(out, out_size);
    }
}

// round 11
// speedup vs baseline: 1.0424x; 1.0424x over previous
#include <cuda_runtime.h>
#include <cstdint>
#include <math.h>

#define NN 8192
#define EPSF 1e-20f
#define NITER 32
#define NCTA 148
#define NTHR 512
#define ROWB 32768               // bytes per H row
#define RDEPTH 4                 // TMA ring slots (power of 2)

// dynamic smem layout
#define SM_MBAR 0                // 4 mbarriers, 16B stride
#define SM_WRED 128              // 2 x 16 warp partials (double-buffered)
#define SM_GPART 1024            // 512 floats (phase-B group partials + reduce scratch)
#define SM_SRED 3072             // 64 floats (phase-B rs partials)
#define SM_T    3328             // 56 floats: this CTA's t_r = (Hp)_row
#define SM_QH   3584             // 56 floats: incremental q_hat for own rows
#define SM_P    3808             // 56 floats: p on own columns (for phaseB)
#define SM_RING 4096             // RDEPTH x 32768 row buffers
#define SMEM_TOTAL (SM_RING + RDEPTH * ROWB)

// ---- device scratch (no allocations allowed) ----
__device__ float g_slab[NCTA * NN];     // 4.85 MB per-CTA Ap partial slabs
__device__ float g_ttpart[NCTA];
__device__ float g_rspart[NCTA];
__device__ float g_r[NN], g_v[NN], g_qh[NN];
__device__ float g_msum[8];             // time-domain metric sums
__device__ float g_fftsum[8];
__device__ unsigned g_flags[NCTA];      // grid-barrier flags (monotone across replays)

// ---------------- PTX helpers ----------------
__device__ __forceinline__ uint32_t sm_u32(const void* p) {
    uint32_t a;
    asm("{ .reg .u64 t; cvta.to.shared.u64 t, %1; cvt.u32.u64 %0, t; }" : "=r"(a) : "l"(p));
    return a;
}
#define MB_INIT(a, c) \
    asm volatile("mbarrier.init.shared.b64 [%0], %1;" :: "r"(a), "r"(c) : "memory")
#define MB_EXPECT(a, b) \
    asm volatile("mbarrier.arrive.expect_tx.shared.b64 _, [%0], %1;" :: "r"(a), "r"(b) : "memory")
#define BULK_LD(dst, src, sz, mb) \
    asm volatile("cp.async.bulk.shared::cta.global.mbarrier::complete_tx::bytes [%0], [%1], %2, [%3];" \
                 :: "r"(dst), "l"(src), "r"(sz), "r"(mb) : "memory")

__device__ __forceinline__ void mb_wait(uint32_t mbar, uint32_t parity) {
    uint32_t done;
    do {
        asm volatile("{ .reg .pred p; mbarrier.try_wait.parity.acquire.cta.shared::cta.b64 p, [%1], %2; "
                     "selp.b32 %0, 1, 0, p; }" : "=r"(done) : "r"(mbar), "r"(parity) : "memory");
    } while (!done);
}

__device__ __forceinline__ void grid_bar(int tid, int bid, unsigned gen) {
    __syncthreads();
    if (tid == 0)
        asm volatile("st.global.release.gpu.u32 [%0], %1;" :: "l"(&g_flags[bid]), "r"(gen) : "memory");
    if (tid < NCTA) {
        unsigned v;
        do {
            asm volatile("ld.global.acquire.gpu.u32 %0, [%1];" : "=r"(v) : "l"(&g_flags[tid]) : "memory");
        } while ((int)(v - gen) < 0);
    }
    __syncthreads();
}

// deterministic 512-thread sum (fixed tree), result broadcast to all threads
__device__ __forceinline__ float block_sum512(float v, float* scr, int tid) {
    for (int o = 16; o; o >>= 1) v += __shfl_xor_sync(0xffffffffu, v, o);
    if ((tid & 31) == 0) scr[tid >> 5] = v;
    __syncthreads();
    if (tid < 16) {
        float w = scr[tid];
        for (int o = 8; o; o >>= 1) w += __shfl_xor_sync(0xffffu, w, o);
        if (tid == 0) scr[0] = w;
    }
    __syncthreads();
    float s = scr[0];
    __syncthreads();
    return s;
}

// ---------------------------------------------------------------------------
// One streaming pass over this CTA's rows via the TMA ring.  (R7 consume loop
// — do not modify.)  pre_done: first RDEPTH loads were issued at the end of
// the previous pass.  pre_next: issue next pass's first RDEPTH loads before
// returning (rows identical every pass; gq keeps parity straight).
// MODE 0: tr = dot(row, preg) -> apa += tr*row, ta += tr*tr, smem t[r] = tr
// MODE 1: tr = xvec[row]      -> apa += tr*row                (setup b = H^T x)
// ---------------------------------------------------------------------------
template<int MODE>
__device__ __forceinline__ float run_pass(const float* __restrict__ H, char* smem,
                                          uint32_t smb, int tid, int row0, int nrows,
                                          unsigned& gq, const float4* preg, float4* apa,
                                          const float* __restrict__ xvec,
                                          bool pre_done, bool pre_next) {
    float* wred = (float*)(smem + SM_WRED);
    float* smt  = (float*)(smem + SM_T);
#pragma unroll
    for (int c = 0; c < 4; c++) apa[c] = make_float4(0.f, 0.f, 0.f, 0.f);
    float ta = 0.f;
    if (!pre_done && tid == 0) {
        for (int k = 0; k < RDEPTH; k++) {
            unsigned u = gq + k;
            uint32_t slot = u & (RDEPTH - 1);
            uint32_t mb = smb + SM_MBAR + slot * 16;
            MB_EXPECT(mb, ROWB);
            BULK_LD(smb + SM_RING + slot * ROWB,
                    (const void*)(H + (size_t)(row0 + k) * NN), (uint32_t)ROWB, mb);
        }
    }
    for (int r = 0; r < nrows; r++) {
        unsigned u = gq + r;
        uint32_t slot = u & (RDEPTH - 1);
        mb_wait(smb + SM_MBAR + slot * 16, (u >> 2) & 1);
        const float4* row4 = (const float4*)(smem + SM_RING + slot * ROWB);
        float4 st[4];
        float d = 0.f;
#pragma unroll
        for (int c = 0; c < 4; c++) {
            st[c] = row4[tid + NTHR * c];
            if (MODE == 0)
                d += st[c].x * preg[c].x + st[c].y * preg[c].y
                   + st[c].z * preg[c].z + st[c].w * preg[c].w;
        }
        float tr;
        if (MODE == 1) {
            tr = xvec[row0 + r];
            __syncthreads();            // all LDS of this slot done before reissue
        } else {
            for (int o = 16; o; o >>= 1) d += __shfl_xor_sync(0xffffffffu, d, o);
            if ((tid & 31) == 0) wred[(r & 1) * 16 + (tid >> 5)] = d;
            __syncthreads();
        }
        if (tid == 0 && r + RDEPTH < nrows) {
            uint32_t mb = smb + SM_MBAR + slot * 16;   // slot(u+RDEPTH) == slot(u)
            MB_EXPECT(mb, ROWB);
            BULK_LD(smb + SM_RING + slot * ROWB,
                    (const void*)(H + (size_t)(row0 + r + RDEPTH) * NN), (uint32_t)ROWB, mb);
        }
        if (MODE == 0) {
            tr = 0.f;
#pragma unroll
            for (int w = 0; w < 16; w++) tr += wred[(r & 1) * 16 + w];
            if (tid == 0) smt[r] = tr;
        }
#pragma unroll
        for (int c = 0; c < 4; c++) {
            apa[c].x += tr * st[c].x; apa[c].y += tr * st[c].y;
            apa[c].z += tr * st[c].z; apa[c].w += tr * st[c].w;
        }
        ta += tr * tr;
    }
    gq += (unsigned)nrows;
    // cross-pass prefetch: all slots drained (last row's __syncthreads covers
    // the LDS); issue next pass's first RDEPTH rows so they land during
    // phaseB + grid barriers.
    if (pre_next && tid == 0) {
        for (int k = 0; k < RDEPTH; k++) {
            unsigned u = gq + k;
            uint32_t slot = u & (RDEPTH - 1);
            uint32_t mb = smb + SM_MBAR + slot * 16;
            MB_EXPECT(mb, ROWB);
            BULK_LD(smb + SM_RING + slot * ROWB,
                    (const void*)(H + (size_t)(row0 + k) * NN), (uint32_t)ROWB, mb);
        }
    }
    return ta;
}

// phase B: slab reduce over own columns + vector update (or setup init).
// p on own columns comes from smem (SM_P), not global.
__device__ __forceinline__ void phaseB(char* smem, int tid, int bid, int c0, int nc,
                                       float alpha, bool setup) {
    float* sgp = (float*)(smem + SM_GPART);
    float* sred = (float*)(smem + SM_SRED);
    float* psm = (float*)(smem + SM_P);
    int g = tid >> 6, tc = tid & 63;
    float part = 0.f;
    if (tc < nc) {
#pragma unroll 4
        for (int cs = g; cs < NCTA; cs += 8) part += g_slab[(size_t)cs * NN + c0 + tc];
    }
    sgp[g * 64 + tc] = part;
    __syncthreads();
    if (tid < nc) {
        float ap = 0.f;
#pragma unroll
        for (int gg = 0; gg < 8; gg++) ap += sgp[gg * 64 + tid];
        int j = c0 + tid;
        float rn;
        if (setup) {
            g_v[j] = 0.f;
            g_r[j] = ap;      // r = b
            rn = ap;
        } else {
            g_v[j] += alpha * psm[tid];
            rn = g_r[j] - alpha * ap;
            g_r[j] = rn;
        }
        sred[tid] = rn * rn;
    }
    __syncthreads();
    if (tid == 0) {
        float s = 0.f;
        for (int i = 0; i < nc; i++) s += sred[i];
        g_rspart[bid] = s;
    }
}

// ---------------------------------------------------------------------------
// The persistent CG kernel: setup + 32 iterations; q_hat accumulated in smem.
// ---------------------------------------------------------------------------
__global__ void __launch_bounds__(NTHR, 1) cgm_persistent(const float* __restrict__ H,
                                                          const float* __restrict__ x) {
    extern __shared__ char smem[];
    int tid = threadIdx.x, bid = blockIdx.x;
    uint32_t smb = sm_u32(smem);
    float* smt = (float*)(smem + SM_T);
    float* smqh = (float*)(smem + SM_QH);
    float* psm = (float*)(smem + SM_P);
    float* scr = (float*)(smem + SM_GPART);
    if (tid == 0) {
        for (int s = 0; s < RDEPTH; s++) MB_INIT(smb + SM_MBAR + s * 16, 1);
    }
    if (tid < 64) smqh[tid] = 0.f;
    __syncthreads();
    unsigned base_gen = g_flags[bid];    // all flags equal at launch (monotone)
    unsigned barn = 0;
    unsigned gq = 0;

    int row0, nrows;
    if (bid < 52) { row0 = bid * 56; nrows = 56; }
    else          { row0 = 2912 + (bid - 52) * 55; nrows = 55; }
    int c0 = row0, nc = nrows;           // same partition for columns

    float4 apa[4], preg[4];
    float rs = 0.f;

    // ---- setup: b = H^T x (rank-1 streaming), then r=b, v=0, rs0 partials ----
    run_pass<1>(H, smem, smb, tid, row0, nrows, gq, preg, apa, x, false, true);
    {
        float4* slab4 = (float4*)(g_slab + (size_t)bid * NN);
#pragma unroll
        for (int c = 0; c < 4; c++) slab4[tid + NTHR * c] = apa[c];
    }
    grid_bar(tid, bid, base_gen + (++barn));
    phaseB(smem, tid, bid, c0, nc, 0.f, true);
    grid_bar(tid, bid, base_gen + (++barn));

    for (int it = 0; it < NITER; it++) {
        // ---- A: beta (parallel reduce), p update (registers + own-col smem) ----
        float rsv = (tid < NCTA) ? g_rspart[tid] : 0.f;
        float rs_new = block_sum512(rsv, scr, tid);
        float beta = (it == 0) ? 0.f : rs_new / (rs + EPSF);
        rs = rs_new;
#pragma unroll
        for (int c = 0; c < 4; c++) {
            int j = tid + NTHR * c;
            float4 rr = ((const float4*)g_r)[j];
            if (it == 0) preg[c] = rr;
            else preg[c] = make_float4(rr.x + beta * preg[c].x, rr.y + beta * preg[c].y,
                                       rr.z + beta * preg[c].z, rr.w + beta * preg[c].w);
            // stash p for own columns (floats 4j..4j+3) into smem for phaseB
            int f0 = 4 * j;
            if (f0 + 3 >= c0 && f0 < c0 + nc) {
                float pv[4] = { preg[c].x, preg[c].y, preg[c].z, preg[c].w };
#pragma unroll
                for (int e = 0; e < 4; e++) {
                    int jj = f0 + e;
                    if (jj >= c0 && jj < c0 + nc) psm[jj - c0] = pv[e];
                }
            }
        }
        // ---- matvec: slab partials of H^T(Hp), tt partials, smem t ----
        float ta = run_pass<0>(H, smem, smb, tid, row0, nrows, gq, preg, apa, nullptr,
                               true, it < NITER - 1);
        {
            float4* slab4 = (float4*)(g_slab + (size_t)bid * NN);
#pragma unroll
            for (int c = 0; c < 4; c++) slab4[tid + NTHR * c] = apa[c];
        }
        if (tid == 0) g_ttpart[bid] = ta;
        grid_bar(tid, bid, base_gen + (++barn));

        // ---- B: alpha (parallel reduce), qh += alpha*t, Ap reduce + v,r + rs ----
        float ttv = (tid < NCTA) ? g_ttpart[tid] : 0.f;
        float tt = block_sum512(ttv, scr, tid);
        float alpha = rs / (tt + EPSF);
        if (tid < nrows) smqh[tid] += alpha * smt[tid];
        __syncthreads();                 // scr (SM_GPART) reuse in phaseB
        phaseB(smem, tid, bid, c0, nc, alpha, false);
        grid_bar(tid, bid, base_gen + (++barn));
    }

    // ---- final: write accumulated q_hat (== H v up to fp rounding) ----
    if (tid < nrows) g_qh[row0 + tid] = smqh[tid];
}

// ---------------------------------------------------------------------------
// Fused tail kernel 1: blocks 0-3 = FFT modes; block 4 = time-domain metrics.
// ---------------------------------------------------------------------------
__global__ void __launch_bounds__(1024) metrics_fft_kernel(const float* __restrict__ x,
                                                           const float* __restrict__ qt,
                                                           const float* __restrict__ vt) {
    int tid = threadIdx.x;
    if (blockIdx.x == 4) {
        float acc[7] = {0.f, 0.f, 0.f, 0.f, 0.f, 0.f, 0.f};
        for (int j = tid; j < NN; j += 1024) {
            float qh = g_qh[j], vv = g_v[j];
            float qtj = qt[j], vtj = vt[j];
            float d0 = qh - x[j];
            float d1 = qh - qtj;
            float d2 = vv - vtj;
            acc[0] += d0 * d0;
            acc[1] += fabsf(d1);
            acc[2] += d1 * d1;
            acc[3] += qtj * qtj;
            acc[4] += fabsf(d2);
            acc[5] += d2 * d2;
            acc[6] += vtj * vtj;
        }
        __shared__ float red[1024];
#pragma unroll
        for (int s = 0; s < 7; s++) {
            red[tid] = acc[s];
            __syncthreads();
            for (int o = 512; o > 0; o >>= 1) {
                if (tid < o) red[tid] += red[tid + o];
                __syncthreads();
            }
            if (tid == 0) g_msum[s] = red[0];
            __syncthreads();
        }
        return;
    }

    // FFT blocks: 8192-pt real FFT via 4096-pt complex FFT (pack even/odd)
    __shared__ float2 Z[4096];
    __shared__ float red[1024];
    int mode = blockIdx.x;

    for (int n = tid; n < 4096; n += 1024) {
        int i0 = 2 * n, i1 = 2 * n + 1;
        float a, b;
        if (mode == 0)      { a = g_qh[i0] - qt[i0]; b = g_qh[i1] - qt[i1]; }
        else if (mode == 1) { a = qt[i0];            b = qt[i1]; }
        else if (mode == 2) { a = g_v[i0] - vt[i0];  b = g_v[i1] - vt[i1]; }
        else                { a = vt[i0];            b = vt[i1]; }
        int r = (int)(__brev((unsigned)n) >> 20);
        Z[r] = make_float2(a, b);
    }
    __syncthreads();

    for (int half = 1; half < 4096; half <<= 1) {
        for (int i = tid; i < 2048; i += 1024) {
            int pos = i & (half - 1);
            int idx1 = ((i ^ pos) << 1) | pos;
            int idx2 = idx1 + half;
            float s, c;
            sincospif((float)pos / (float)half, &s, &c);
            float2 z2 = Z[idx2];
            float2 t = make_float2(c * z2.x + s * z2.y, c * z2.y - s * z2.x);
            float2 z1 = Z[idx1];
            Z[idx2] = make_float2(z1.x - t.x, z1.y - t.y);
            Z[idx1] = make_float2(z1.x + t.x, z1.y + t.y);
        }
        __syncthreads();
    }

    float sabs = 0.f, ssq = 0.f;
    for (int k = tid; k <= 4096; k += 1024) {
        float2 Zk = Z[k & 4095];
        float2 Zm = Z[(4096 - k) & 4095];
        float2 Zmc = make_float2(Zm.x, -Zm.y);
        float2 Fe = make_float2(0.5f * (Zk.x + Zmc.x), 0.5f * (Zk.y + Zmc.y));
        float2 Fd = make_float2(Zk.x - Zmc.x, Zk.y - Zmc.y);
        float2 Fo = make_float2(0.5f * Fd.y, -0.5f * Fd.x);
        float s, c;
        sincospif((float)k / 4096.0f, &s, &c);
        float Xr = Fe.x + (c * Fo.x + s * Fo.y);
        float Xi = Fe.y + (c * Fo.y - s * Fo.x);
        float m2 = Xr * Xr + Xi * Xi;
        sabs += sqrtf(m2);
        ssq += m2;
    }
    red[tid] = sabs;
    __syncthreads();
    for (int s = 512; s > 0; s >>= 1) {
        if (tid < s) red[tid] += red[tid + s];
        __syncthreads();
    }
    if (tid == 0) g_fftsum[2 * mode] = red[0];
    __syncthreads();
    red[tid] = ssq;
    __syncthreads();
    for (int s = 512; s > 0; s >>= 1) {
        if (tid < s) red[tid] += red[tid + s];
        __syncthreads();
    }
    if (tid == 0) g_fftsum[2 * mode + 1] = red[0];
}

// ---------------------------------------------------------------------------
// Fused tail kernel 2: copy v (all blocks) + scalars (block 0 / thread 0).
// ---------------------------------------------------------------------------
__global__ void finalize_out_kernel(float* __restrict__ out, int out_size) {
    int j = blockIdx.x * 128 + threadIdx.x;
    if (j < out_size) {
        if (j < NN) out[j] = g_v[j];
        else if (j >= NN + 11) out[j] = 0.f;
    }
    if (blockIdx.x == 0 && threadIdx.x == 0) {
        float res[11];
        res[0]  = sqrtf(g_msum[0]);
        res[1]  = g_msum[1] / (float)NN;
        res[2]  = g_msum[2] / (g_msum[3] + EPSF);
        res[3]  = g_msum[4] / (float)NN;
        res[4]  = g_msum[5] / (g_msum[6] + EPSF);
        res[5]  = g_msum[2] / (float)NN;
        res[6]  = g_msum[5] / (float)NN;
        res[7]  = g_fftsum[0] / 4097.0f;
        res[8]  = g_fftsum[1] / (g_fftsum[3] + EPSF);
        res[9]  = g_fftsum[4] / 4097.0f;
        res[10] = g_fftsum[5] / (g_fftsum[7] + EPSF);
        for (int k = 0; k < 11; k++)
            if (NN + k < out_size) out[NN + k] = res[k];
    }
}

extern "C" void kernel_launch(void* const* d_in, const int* in_sizes, int n_in,
                              void* d_out, int out_size) {
    const float* H = nullptr;
    const float* x = nullptr;
    const float* vt = nullptr;
    const float* qt = nullptr;
    int vecseen = 0;
    for (int i = 0; i < n_in; i++) {
        if (in_sizes[i] == NN * NN) {
            H = (const float*)d_in[i];
        } else if (in_sizes[i] == NN) {
            if (vecseen == 0)      x  = (const float*)d_in[i];
            else if (vecseen == 1) vt = (const float*)d_in[i];
            else if (vecseen == 2) qt = (const float*)d_in[i];
            vecseen++;
        }
    }
    float* out = (float*)d_out;

    cudaFuncSetAttribute(cgm_persistent, cudaFuncAttributeMaxDynamicSharedMemorySize,
                         SMEM_TOTAL);

    cgm_persistent<<<NCTA, NTHR, SMEM_TOTAL>>>(H, x);
    metrics_fft_kernel<<<5, 1024>>>(x, qt, vt);
    {
        int nblk = (out_size + 127) / 128;
        if (nblk < 1) nblk = 1;
        finalize_out_kernel<<<nblk, 128>>>(out, out_size);
    }
}

// round 12
// speedup vs baseline: 1.1498x; 1.1030x over previous
#include <cuda_runtime.h>
#include <cuda_fp16.h>
#include <cstdint>
#include <math.h>

#define NN 8192
#define EPSF 1e-20f
#define NITER 32
#define NCTA 148
#define NTHR 512
#define ROWB 16384               // bytes per fp16 H row
#define RDEPTH 8                 // TMA ring slots (power of 2)

// dynamic smem layout
#define SM_MBAR 0                // 8 mbarriers, 16B stride
#define SM_WRED 128              // 2 x 16 warp partials (double-buffered)
#define SM_GPART 1024            // 512 floats (phase-B group partials + reduce scratch)
#define SM_SRED 3072             // 64 floats (phase-B rs partials)
#define SM_T    3328             // 56 floats: this CTA's t_r = (Hp)_row
#define SM_QH   3584             // 56 floats: incremental q_hat for own rows
#define SM_P    3808             // 56 floats: p on own columns (for phaseB)
#define SM_RING 4096             // RDEPTH x 16384 row buffers
#define SMEM_TOTAL (SM_RING + RDEPTH * ROWB)

// ---- device scratch (no allocations allowed) ----
__device__ __half g_Hh[(size_t)NN * NN];   // 134 MB fp16 copy of H
__device__ float g_slab[NCTA * NN];        // 4.85 MB per-CTA Ap partial slabs
__device__ float g_ttpart[NCTA];
__device__ float g_rspart[NCTA];
__device__ float g_r[NN], g_v[NN], g_qh[NN];
__device__ float g_msum[8];
__device__ float g_fftsum[8];
__device__ unsigned g_flags[NCTA];         // grid-barrier flags (monotone)

// ---------------- PTX helpers ----------------
__device__ __forceinline__ uint32_t sm_u32(const void* p) {
    uint32_t a;
    asm("{ .reg .u64 t; cvta.to.shared.u64 t, %1; cvt.u32.u64 %0, t; }" : "=r"(a) : "l"(p));
    return a;
}
#define MB_INIT(a, c) \
    asm volatile("mbarrier.init.shared.b64 [%0], %1;" :: "r"(a), "r"(c) : "memory")
#define MB_EXPECT(a, b) \
    asm volatile("mbarrier.arrive.expect_tx.shared.b64 _, [%0], %1;" :: "r"(a), "r"(b) : "memory")
#define BULK_LD(dst, src, sz, mb) \
    asm volatile("cp.async.bulk.shared::cta.global.mbarrier::complete_tx::bytes [%0], [%1], %2, [%3];" \
                 :: "r"(dst), "l"(src), "r"(sz), "r"(mb) : "memory")

__device__ __forceinline__ void mb_wait(uint32_t mbar, uint32_t parity) {
    uint32_t done;
    do {
        asm volatile("{ .reg .pred p; mbarrier.try_wait.parity.acquire.cta.shared::cta.b64 p, [%1], %2; "
                     "selp.b32 %0, 1, 0, p; }" : "=r"(done) : "r"(mbar), "r"(parity) : "memory");
    } while (!done);
}

__device__ __forceinline__ void grid_bar(int tid, int bid, unsigned gen) {
    __syncthreads();
    if (tid == 0)
        asm volatile("st.global.release.gpu.u32 [%0], %1;" :: "l"(&g_flags[bid]), "r"(gen) : "memory");
    if (tid < NCTA) {
        unsigned v;
        do {
            asm volatile("ld.global.acquire.gpu.u32 %0, [%1];" : "=r"(v) : "l"(&g_flags[tid]) : "memory");
        } while ((int)(v - gen) < 0);
    }
    __syncthreads();
}

// deterministic 512-thread sum (fixed tree), result broadcast to all threads
__device__ __forceinline__ float block_sum512(float v, float* scr, int tid) {
    for (int o = 16; o; o >>= 1) v += __shfl_xor_sync(0xffffffffu, v, o);
    if ((tid & 31) == 0) scr[tid >> 5] = v;
    __syncthreads();
    if (tid < 16) {
        float w = scr[tid];
        for (int o = 8; o; o >>= 1) w += __shfl_xor_sync(0xffffu, w, o);
        if (tid == 0) scr[0] = w;
    }
    __syncthreads();
    float s = scr[0];
    __syncthreads();
    return s;
}

// ---------------------------------------------------------------------------
// fp32 H -> fp16 g_Hh, 16 floats per thread, fully coalesced.
// ---------------------------------------------------------------------------
__global__ __launch_bounds__(256) void convert_h_kernel(const float* __restrict__ H) {
    size_t t = (size_t)blockIdx.x * 256 + threadIdx.x;
    const float4* h4 = (const float4*)H + t * 4;
    uint4 o[2];
    __half2* hh = (__half2*)o;
#pragma unroll
    for (int k = 0; k < 4; k++) {
        float4 a = h4[k];
        hh[2 * k]     = __floats2half2_rn(a.x, a.y);
        hh[2 * k + 1] = __floats2half2_rn(a.z, a.w);
    }
    uint4* dst = (uint4*)g_Hh + t * 2;
    dst[0] = o[0];
    dst[1] = o[1];
}

// ---------------------------------------------------------------------------
// One streaming pass over this CTA's rows (fp16) via the TMA ring.
// Thread tid owns 16 columns: [8t..8t+7] and [8t+4096..8t+4096+7],
// i.e. float4 indices 2t, 2t+1, 2t+1024, 2t+1025.  preg/apaf in fp32.
// MODE 0: tr = dot(row, p) -> apaf += tr*row, ta += tr*tr, smem t[r] = tr
// MODE 1: tr = xvec[row]   -> apaf += tr*row               (setup b = H^T x)
// pre_done / pre_next: cross-pass TMA prefetch of the first RDEPTH rows.
// ---------------------------------------------------------------------------
template<int MODE>
__device__ __forceinline__ float run_pass(char* smem, uint32_t smb, int tid,
                                          int row0, int nrows, unsigned& gq,
                                          const float* pf, float* apaf,
                                          const float* __restrict__ xvec,
                                          bool pre_done, bool pre_next) {
    float* wred = (float*)(smem + SM_WRED);
    float* smt  = (float*)(smem + SM_T);
    const __half* Hb = g_Hh;
#pragma unroll
    for (int i = 0; i < 16; i++) apaf[i] = 0.f;
    float ta = 0.f;
    if (!pre_done && tid == 0) {
        for (int k = 0; k < RDEPTH; k++) {
            unsigned u = gq + k;
            uint32_t slot = u & (RDEPTH - 1);
            uint32_t mb = smb + SM_MBAR + slot * 16;
            MB_EXPECT(mb, ROWB);
            BULK_LD(smb + SM_RING + slot * ROWB,
                    (const void*)(Hb + (size_t)(row0 + k) * NN), (uint32_t)ROWB, mb);
        }
    }
    for (int r = 0; r < nrows; r++) {
        unsigned u = gq + r;
        uint32_t slot = u & (RDEPTH - 1);
        mb_wait(smb + SM_MBAR + slot * 16, (u >> 3) & 1);
        const uint4* rowu = (const uint4*)(smem + SM_RING + slot * ROWB);
        float fl[16];
        float d = 0.f;
#pragma unroll
        for (int c = 0; c < 2; c++) {
            uint4 raw = rowu[tid + NTHR * c];
            const __half2* hp = (const __half2*)&raw;
#pragma unroll
            for (int e = 0; e < 4; e++) {
                float2 f = __half22float2(hp[e]);
                fl[c * 8 + 2 * e]     = f.x;
                fl[c * 8 + 2 * e + 1] = f.y;
            }
            if (MODE == 0) {
#pragma unroll
                for (int e = 0; e < 8; e++) d += fl[c * 8 + e] * pf[c * 8 + e];
            }
        }
        float tr;
        if (MODE == 1) {
            tr = xvec[row0 + r];
            __syncthreads();            // all LDS of this slot done before reissue
        } else {
            for (int o = 16; o; o >>= 1) d += __shfl_xor_sync(0xffffffffu, d, o);
            if ((tid & 31) == 0) wred[(r & 1) * 16 + (tid >> 5)] = d;
            __syncthreads();
        }
        if (tid == 0 && r + RDEPTH < nrows) {
            uint32_t mb = smb + SM_MBAR + slot * 16;   // slot(u+RDEPTH) == slot(u)
            MB_EXPECT(mb, ROWB);
            BULK_LD(smb + SM_RING + slot * ROWB,
                    (const void*)(Hb + (size_t)(row0 + r + RDEPTH) * NN), (uint32_t)ROWB, mb);
        }
        if (MODE == 0) {
            tr = 0.f;
#pragma unroll
            for (int w = 0; w < 16; w++) tr += wred[(r & 1) * 16 + w];
            if (tid == 0) smt[r] = tr;
        }
#pragma unroll
        for (int i = 0; i < 16; i++) apaf[i] += tr * fl[i];
        ta += tr * tr;
    }
    gq += (unsigned)nrows;
    if (pre_next && tid == 0) {
        for (int k = 0; k < RDEPTH; k++) {
            unsigned u = gq + k;
            uint32_t slot = u & (RDEPTH - 1);
            uint32_t mb = smb + SM_MBAR + slot * 16;
            MB_EXPECT(mb, ROWB);
            BULK_LD(smb + SM_RING + slot * ROWB,
                    (const void*)(Hb + (size_t)(row0 + k) * NN), (uint32_t)ROWB, mb);
        }
    }
    return ta;
}

// write apaf (16 cols per thread) to this CTA's slab
__device__ __forceinline__ void slab_store(int bid, int tid, const float* apaf) {
    float4* slab4 = (float4*)(g_slab + (size_t)bid * NN);
    const float4* a4 = (const float4*)apaf;
    slab4[2 * tid]        = a4[0];
    slab4[2 * tid + 1]    = a4[1];
    slab4[2 * tid + 1024] = a4[2];
    slab4[2 * tid + 1025] = a4[3];
}

// phase B: slab reduce over own columns + vector update (or setup init).
__device__ __forceinline__ void phaseB(char* smem, int tid, int bid, int c0, int nc,
                                       float alpha, bool setup) {
    float* sgp = (float*)(smem + SM_GPART);
    float* sred = (float*)(smem + SM_SRED);
    float* psm = (float*)(smem + SM_P);
    int g = tid >> 6, tc = tid & 63;
    float part = 0.f;
    if (tc < nc) {
#pragma unroll 4
        for (int cs = g; cs < NCTA; cs += 8) part += g_slab[(size_t)cs * NN + c0 + tc];
    }
    sgp[g * 64 + tc] = part;
    __syncthreads();
    if (tid < nc) {
        float ap = 0.f;
#pragma unroll
        for (int gg = 0; gg < 8; gg++) ap += sgp[gg * 64 + tid];
        int j = c0 + tid;
        float rn;
        if (setup) {
            g_v[j] = 0.f;
            g_r[j] = ap;      // r = b
            rn = ap;
        } else {
            g_v[j] += alpha * psm[tid];
            rn = g_r[j] - alpha * ap;
            g_r[j] = rn;
        }
        sred[tid] = rn * rn;
    }
    __syncthreads();
    if (tid == 0) {
        float s = 0.f;
        for (int i = 0; i < nc; i++) s += sred[i];
        g_rspart[bid] = s;
    }
}

// ---------------------------------------------------------------------------
// The persistent CG kernel: setup + 32 iterations; q_hat accumulated in smem.
// ---------------------------------------------------------------------------
__global__ void __launch_bounds__(NTHR, 1) cgm_persistent(const float* __restrict__ x) {
    extern __shared__ char smem[];
    int tid = threadIdx.x, bid = blockIdx.x;
    uint32_t smb = sm_u32(smem);
    float* smt = (float*)(smem + SM_T);
    float* smqh = (float*)(smem + SM_QH);
    float* psm = (float*)(smem + SM_P);
    float* scr = (float*)(smem + SM_GPART);
    if (tid == 0) {
        for (int s = 0; s < RDEPTH; s++) MB_INIT(smb + SM_MBAR + s * 16, 1);
    }
    if (tid < 64) smqh[tid] = 0.f;
    __syncthreads();
    unsigned base_gen = g_flags[bid];
    unsigned barn = 0;
    unsigned gq = 0;

    int row0, nrows;
    if (bid < 52) { row0 = bid * 56; nrows = 56; }
    else          { row0 = 2912 + (bid - 52) * 55; nrows = 55; }
    int c0 = row0, nc = nrows;

    float apaf[16], pfv[16];
    float rs = 0.f;

    // float4 indices of this thread's 16 columns
    const int fidx0 = 2 * tid, fidx1 = 2 * tid + 1;
    const int fidx2 = 2 * tid + 1024, fidx3 = 2 * tid + 1025;

    // ---- setup: b = H^T x (rank-1 streaming), then r=b, v=0, rs0 partials ----
    run_pass<1>(smem, smb, tid, row0, nrows, gq, pfv, apaf, x, false, true);
    slab_store(bid, tid, apaf);
    grid_bar(tid, bid, base_gen + (++barn));
    phaseB(smem, tid, bid, c0, nc, 0.f, true);
    grid_bar(tid, bid, base_gen + (++barn));

    for (int it = 0; it < NITER; it++) {
        // ---- A: beta (parallel reduce), p update (regs + own-col smem) ----
        float rsv = (tid < NCTA) ? g_rspart[tid] : 0.f;
        float rs_new = block_sum512(rsv, scr, tid);
        float beta = (it == 0) ? 0.f : rs_new / (rs + EPSF);
        rs = rs_new;
        int fidx[4] = { fidx0, fidx1, fidx2, fidx3 };
#pragma unroll
        for (int c = 0; c < 4; c++) {
            float4 rr = ((const float4*)g_r)[fidx[c]];
            float4 pv;
            if (it == 0) pv = rr;
            else pv = make_float4(rr.x + beta * pfv[4 * c],     rr.y + beta * pfv[4 * c + 1],
                                  rr.z + beta * pfv[4 * c + 2], rr.w + beta * pfv[4 * c + 3]);
            pfv[4 * c] = pv.x; pfv[4 * c + 1] = pv.y;
            pfv[4 * c + 2] = pv.z; pfv[4 * c + 3] = pv.w;
            // stash p for own columns into smem for phaseB
            int col0 = 4 * fidx[c];
            if (col0 + 3 >= c0 && col0 < c0 + nc) {
#pragma unroll
                for (int e = 0; e < 4; e++) {
                    int jj = col0 + e;
                    if (jj >= c0 && jj < c0 + nc) psm[jj - c0] = pfv[4 * c + e];
                }
            }
        }
        // ---- matvec: slab partials of H^T(Hp), tt partials, smem t ----
        float ta = run_pass<0>(smem, smb, tid, row0, nrows, gq, pfv, apaf, nullptr,
                               true, it < NITER - 1);
        slab_store(bid, tid, apaf);
        if (tid == 0) g_ttpart[bid] = ta;
        grid_bar(tid, bid, base_gen + (++barn));

        // ---- B: alpha (parallel reduce), qh += alpha*t, Ap reduce + v,r + rs ----
        float ttv = (tid < NCTA) ? g_ttpart[tid] : 0.f;
        float tt = block_sum512(ttv, scr, tid);
        float alpha = rs / (tt + EPSF);
        if (tid < nrows) smqh[tid] += alpha * smt[tid];
        __syncthreads();                 // scr (SM_GPART) reuse in phaseB
        phaseB(smem, tid, bid, c0, nc, alpha, false);
        grid_bar(tid, bid, base_gen + (++barn));
    }

    // ---- final: write accumulated q_hat ----
    if (tid < nrows) g_qh[row0 + tid] = smqh[tid];
}

// ---------------------------------------------------------------------------
// Fused tail kernel 1: blocks 0-3 = FFT modes; block 4 = time-domain metrics.
// ---------------------------------------------------------------------------
__global__ void __launch_bounds__(1024) metrics_fft_kernel(const float* __restrict__ x,
                                                           const float* __restrict__ qt,
                                                           const float* __restrict__ vt) {
    int tid = threadIdx.x;
    if (blockIdx.x == 4) {
        float acc[7] = {0.f, 0.f, 0.f, 0.f, 0.f, 0.f, 0.f};
        for (int j = tid; j < NN; j += 1024) {
            float qh = g_qh[j], vv = g_v[j];
            float qtj = qt[j], vtj = vt[j];
            float d0 = qh - x[j];
            float d1 = qh - qtj;
            float d2 = vv - vtj;
            acc[0] += d0 * d0;
            acc[1] += fabsf(d1);
            acc[2] += d1 * d1;
            acc[3] += qtj * qtj;
            acc[4] += fabsf(d2);
            acc[5] += d2 * d2;
            acc[6] += vtj * vtj;
        }
        __shared__ float red[1024];
#pragma unroll
        for (int s = 0; s < 7; s++) {
            red[tid] = acc[s];
            __syncthreads();
            for (int o = 512; o > 0; o >>= 1) {
                if (tid < o) red[tid] += red[tid + o];
                __syncthreads();
            }
            if (tid == 0) g_msum[s] = red[0];
            __syncthreads();
        }
        return;
    }

    __shared__ float2 Z[4096];
    __shared__ float red[1024];
    int mode = blockIdx.x;

    for (int n = tid; n < 4096; n += 1024) {
        int i0 = 2 * n, i1 = 2 * n + 1;
        float a, b;
        if (mode == 0)      { a = g_qh[i0] - qt[i0]; b = g_qh[i1] - qt[i1]; }
        else if (mode == 1) { a = qt[i0];            b = qt[i1]; }
        else if (mode == 2) { a = g_v[i0] - vt[i0];  b = g_v[i1] - vt[i1]; }
        else                { a = vt[i0];            b = vt[i1]; }
        int r = (int)(__brev((unsigned)n) >> 20);
        Z[r] = make_float2(a, b);
    }
    __syncthreads();

    for (int half = 1; half < 4096; half <<= 1) {
        for (int i = tid; i < 2048; i += 1024) {
            int pos = i & (half - 1);
            int idx1 = ((i ^ pos) << 1) | pos;
            int idx2 = idx1 + half;
            float s, c;
            sincospif((float)pos / (float)half, &s, &c);
            float2 z2 = Z[idx2];
            float2 t = make_float2(c * z2.x + s * z2.y, c * z2.y - s * z2.x);
            float2 z1 = Z[idx1];
            Z[idx2] = make_float2(z1.x - t.x, z1.y - t.y);
            Z[idx1] = make_float2(z1.x + t.x, z1.y + t.y);
        }
        __syncthreads();
    }

    float sabs = 0.f, ssq = 0.f;
    for (int k = tid; k <= 4096; k += 1024) {
        float2 Zk = Z[k & 4095];
        float2 Zm = Z[(4096 - k) & 4095];
        float2 Zmc = make_float2(Zm.x, -Zm.y);
        float2 Fe = make_float2(0.5f * (Zk.x + Zmc.x), 0.5f * (Zk.y + Zmc.y));
        float2 Fd = make_float2(Zk.x - Zmc.x, Zk.y - Zmc.y);
        float2 Fo = make_float2(0.5f * Fd.y, -0.5f * Fd.x);
        float s, c;
        sincospif((float)k / 4096.0f, &s, &c);
        float Xr = Fe.x + (c * Fo.x + s * Fo.y);
        float Xi = Fe.y + (c * Fo.y - s * Fo.x);
        float m2 = Xr * Xr + Xi * Xi;
        sabs += sqrtf(m2);
        ssq += m2;
    }
    red[tid] = sabs;
    __syncthreads();
    for (int s = 512; s > 0; s >>= 1) {
        if (tid < s) red[tid] += red[tid + s];
        __syncthreads();
    }
    if (tid == 0) g_fftsum[2 * mode] = red[0];
    __syncthreads();
    red[tid] = ssq;
    __syncthreads();
    for (int s = 512; s > 0; s >>= 1) {
        if (tid < s) red[tid] += red[tid + s];
        __syncthreads();
    }
    if (tid == 0) g_fftsum[2 * mode + 1] = red[0];
}

// ---------------------------------------------------------------------------
// Fused tail kernel 2: copy v (all blocks) + scalars (block 0 / thread 0).
// ---------------------------------------------------------------------------
__global__ void finalize_out_kernel(float* __restrict__ out, int out_size) {
    int j = blockIdx.x * 128 + threadIdx.x;
    if (j < out_size) {
        if (j < NN) out[j] = g_v[j];
        else if (j >= NN + 11) out[j] = 0.f;
    }
    if (blockIdx.x == 0 && threadIdx.x == 0) {
        float res[11];
        res[0]  = sqrtf(g_msum[0]);
        res[1]  = g_msum[1] / (float)NN;
        res[2]  = g_msum[2] / (g_msum[3] + EPSF);
        res[3]  = g_msum[4] / (float)NN;
        res[4]  = g_msum[5] / (g_msum[6] + EPSF);
        res[5]  = g_msum[2] / (float)NN;
        res[6]  = g_msum[5] / (float)NN;
        res[7]  = g_fftsum[0] / 4097.0f;
        res[8]  = g_fftsum[1] / (g_fftsum[3] + EPSF);
        res[9]  = g_fftsum[4] / 4097.0f;
        res[10] = g_fftsum[5] / (g_fftsum[7] + EPSF);
        for (int k = 0; k < 11; k++)
            if (NN + k < out_size) out[NN + k] = res[k];
    }
}

extern "C" void kernel_launch(void* const* d_in, const int* in_sizes, int n_in,
                              void* d_out, int out_size) {
    const float* H = nullptr;
    const float* x = nullptr;
    const float* vt = nullptr;
    const float* qt = nullptr;
    int vecseen = 0;
    for (int i = 0; i < n_in; i++) {
        if (in_sizes[i] == NN * NN) {
            H = (const float*)d_in[i];
        } else if (in_sizes[i] == NN) {
            if (vecseen == 0)      x  = (const float*)d_in[i];
            else if (vecseen == 1) vt = (const float*)d_in[i];
            else if (vecseen == 2) qt = (const float*)d_in[i];
            vecseen++;
        }
    }
    float* out = (float*)d_out;

    cudaFuncSetAttribute(cgm_persistent, cudaFuncAttributeMaxDynamicSharedMemorySize,
                         SMEM_TOTAL);

    // fp32 H -> fp16 copy (deterministic, repeated each replay)
    convert_h_kernel<<<NN * NN / (256 * 16), 256>>>(H);

    cgm_persistent<<<NCTA, NTHR, SMEM_TOTAL>>>(x);
    metrics_fft_kernel<<<5, 1024>>>(x, qt, vt);
    {
        int nblk = (out_size + 127) / 128;
        if (nblk < 1) nblk = 1;
        finalize_out_kernel<<<nblk, 128>>>(out, out_size);
    }
}